// round 15
// baseline (speedup 1.0000x reference)
#include <cuda_runtime.h>

// Cox partial-likelihood loss, n = 8192 — single fused kernel, critical-path
// optimized:
//   * CHUNK=256 (32 chunks): shorter bitonic network (36 stages, only 6 smem
//     barrier stages) and 9-step searches.
//   * Per-chunk ready flags (st.release / ld.acquire) instead of a global
//     sort barrier — search of chunk c starts the moment chunk c is sorted.
//   * Chunk contributions accumulated into g_S[i] as FIXED-POINT u64 via
//     RED.ADD (no return). Integer addition is commutative -> bitwise
//     deterministic independent of arrival order. One u64 load replaces the
//     16-float partial gather.
//   * Two-level election (tile, then global) for the loss reduction; all fp
//     sums fixed-order.
//
// Grid (32 chunks x 16 i-tiles) = 512 blocks x 256 thr; occupancy limit 4
// blocks/SM -> capacity 592 blocks >= 512: whole grid co-resident, spins safe.
// No device allocations, graph-capturable, deterministic.

#define N        8192
#define CHUNK    256
#define NCHUNK   32
#define BLOCK    256
#define TILE     512           // i's per tile (2 per thread)
#define NTILE    16            // N / TILE
#define EPS_F    1e-8f
#define FPSCALE  4294967296.0  // 2^32

__device__ float              g_ts[N];                    // chunk-sorted t
__device__ float              g_sf[NCHUNK * (CHUNK + 1)]; // suffix + sentinel
__device__ unsigned long long g_S[N];                     // fixed-point S_i
__device__ float              g_bsum[NTILE];
__device__ int                g_flag[NCHUNK];             // zero-init
__device__ int                g_done_it[NTILE];           // zero-init
__device__ int                g_done_final;               // zero-init

__device__ __forceinline__ void bstage_shfl(float& key, float& val,
                                            int j, int k, int tid) {
    const float bk = __shfl_xor_sync(0xffffffffu, key, j);
    const float bv = __shfl_xor_sync(0xffffffffu, val, j);
    const bool lower = (tid & j) == 0;
    const bool up    = (tid & k) == 0;
    const bool take_b = (up == lower) ? (bk < key) : (bk > key);
    if (take_b) { key = bk; val = bv; }
}

__global__ __launch_bounds__(BLOCK, 4) void cox_fused(
    const float* __restrict__ risk,
    const float* __restrict__ t,
    const float* __restrict__ e,
    float* __restrict__ out,
    int n)
{
    __shared__ float sk[CHUNK];
    __shared__ float sv[CHUNK];
    __shared__ float ts[CHUNK];
    __shared__ float sf[CHUNK + 1];
    __shared__ float red[BLOCK];
    __shared__ float wsum[BLOCK / 32];
    __shared__ int   flag;

    const int c    = blockIdx.x;         // chunk  0..31
    const int ib   = blockIdx.y;         // i-tile 0..15
    const int tid  = threadIdx.x;
    const int lane = tid & 31;
    const int w    = tid >> 5;

    // prefetch search keys before any waiting (latency overlapped with spin)
    const int   i0 = ib * TILE + tid;
    const int   i1 = i0 + BLOCK;
    const float t0 = t[i0];
    const float t1 = t[i1];

    if (ib == 0) {
        // ============== sorter block for chunk c ==========================
        const int base = c * CHUNK;
        float key = t[base + tid];
        float val = expf(risk[base + tid]);

        // k = 2..32 entirely in registers
#pragma unroll
        for (int k = 2; k <= 32; k <<= 1)
#pragma unroll
            for (int j = k >> 1; j >= 1; j >>= 1)
                bstage_shfl(key, val, j, k, tid);

        // k = 64..256: j>=32 via smem (6 stages), j<32 via shfl
        for (int k = 64; k <= CHUNK; k <<= 1) {
            for (int j = k >> 1; j >= 32; j >>= 1) {
                sk[tid] = key; sv[tid] = val;
                __syncthreads();
                const int p = tid ^ j;
                const float bk = sk[p], bv = sv[p];
                const bool lower = (tid & j) == 0;
                const bool up    = (tid & k) == 0;
                const bool take_b = (up == lower) ? (bk < key) : (bk > key);
                if (take_b) { key = bk; val = bv; }
                __syncthreads();
            }
#pragma unroll
            for (int j = 16; j >= 1; j >>= 1)
                bstage_shfl(key, val, j, k, tid);
        }

        // inclusive suffix scan: warp shfl + cross-warp fixup
        float v = val;
#pragma unroll
        for (int off = 1; off < 32; off <<= 1) {
            const float x = __shfl_down_sync(0xffffffffu, v, off);
            if (lane + off < 32) v += x;
        }
        if (lane == 0) wsum[w] = v;
        __syncthreads();
        float add = 0.0f;
        for (int ww = w + 1; ww < BLOCK / 32; ww++)   // fixed order
            add += wsum[ww];
        v += add;

        // publish: smem (for own search) + global (for other tiles)
        ts[tid] = key;
        sf[tid] = v;
        if (tid == 0) sf[CHUNK] = 0.0f;
        g_ts[c * CHUNK + tid] = key;
        g_sf[c * (CHUNK + 1) + tid] = v;
        if (tid == 0) g_sf[c * (CHUNK + 1) + CHUNK] = 0.0f;
        __syncthreads();
        if (tid == 0)      // release: orders all prior STGs before the flag
            asm volatile("st.global.release.gpu.b32 [%0], %1;"
                         :: "l"(&g_flag[c]), "r"(1) : "memory");
    } else {
        // ============== searcher block: wait for chunk c, stage tables ====
        if (tid == 0) {
            int v;
            do {
                asm volatile("ld.global.acquire.gpu.b32 %0, [%1];"
                             : "=r"(v) : "l"(&g_flag[c]) : "memory");
            } while (v == 0);
        }
        __syncthreads();
        ts[tid] = g_ts[c * CHUNK + tid];
        for (int idx = tid; idx < CHUNK + 1; idx += BLOCK)
            sf[idx] = g_sf[c * (CHUNK + 1) + idx];
        __syncthreads();
    }

    // ================= search: two interleaved lower_bounds ===============
    int p0 = 0, p1 = 0;
#pragma unroll
    for (int bit = CHUNK >> 1; bit >= 1; bit >>= 1) {
        const float a0 = ts[p0 + bit - 1];
        const float a1 = ts[p1 + bit - 1];
        if (a0 < t0) p0 += bit;
        if (a1 < t1) p1 += bit;
    }
    if (ts[p0] < t0) p0++;               // allow pos == CHUNK
    if (ts[p1] < t1) p1++;

    // fixed-point contribution: integer adds -> order-independent result
    const unsigned long long q0 =
        (unsigned long long)__double2ll_rn((double)sf[p0] * FPSCALE);
    const unsigned long long q1 =
        (unsigned long long)__double2ll_rn((double)sf[p1] * FPSCALE);
    atomicAdd(&g_S[i0], q0);             // RED.ADD.64, no return
    atomicAdd(&g_S[i1], q1);

    // ================= tile election (32 chunk-blocks per tile) ===========
    __threadfence();
    __syncthreads();
    if (tid == 0)
        flag = (atomicAdd(&g_done_it[ib], 1) == NCHUNK - 1);
    __syncthreads();
    if (!flag) return;

    __threadfence();                     // acquire: all RED.ADDs visible

    const unsigned long long v0 = g_S[i0];
    const unsigned long long v1 = g_S[i1];
    g_S[i0] = 0ull;                      // reset for next graph replay
    g_S[i1] = 0ull;

    const float S0 = (float)((double)v0 * (1.0 / FPSCALE));
    const float S1 = (float)((double)v1 * (1.0 / FPSCALE));

    float acc = (risk[i0] - logf(S0 + EPS_F)) * e[i0]
              + (risk[i1] - logf(S1 + EPS_F)) * e[i1];

    // fixed-order block reduction of 256 values
    red[tid] = acc;
    __syncthreads();
    if (tid < 128) red[tid] += red[tid + 128];
    __syncthreads();
    if (tid < 64)  red[tid] += red[tid + 64];
    __syncthreads();
    if (tid < 32) {
        float v = red[tid] + red[tid + 32];
#pragma unroll
        for (int off = 16; off > 0; off >>= 1)
            v += __shfl_down_sync(0xffffffffu, v, off);

        if (tid == 0) {
            g_bsum[ib] = v;
            __threadfence();
            if (atomicAdd(&g_done_final, 1) == NTILE - 1) {
                __threadfence();
                float total = 0.0f;
                for (int b = 0; b < NTILE; b++)   // fixed order
                    total += __ldcg(&g_bsum[b]);
                out[0] = -total / (float)n;

                // reset all control state for the next graph replay
                g_done_final = 0;
                for (int b = 0; b < NTILE; b++)  g_done_it[b] = 0;
                for (int cc = 0; cc < NCHUNK; cc++) g_flag[cc] = 0;
                __threadfence();
            }
        }
    }
}

// ---------------------------------------------------------------- launch
extern "C" void kernel_launch(void* const* d_in, const int* in_sizes, int n_in,
                              void* d_out, int out_size) {
    const float* risk = (const float*)d_in[0];
    const float* t    = (const float*)d_in[1];
    const float* e    = (const float*)d_in[2];
    float* out = (float*)d_out;

    const int n = in_sizes[0];   // 8192

    cox_fused<<<dim3(NCHUNK, NTILE), BLOCK>>>(risk, t, e, out, n);
}

// round 16
// speedup vs baseline: 1.0935x; 1.0935x over previous
#include <cuda_runtime.h>

// Cox partial-likelihood loss, n = 8192 — single fused kernel, critical-path
// optimized:
//   * CHUNK=256 (32 chunks): shorter bitonic network (36 stages, only 6 smem
//     barrier stages) and 9-step searches.
//   * Per-chunk ready flags (st.release / ld.acquire) instead of a global
//     sort barrier — search of chunk c starts the moment chunk c is sorted.
//   * Chunk contributions accumulated into g_S[i] as FIXED-POINT u64 via
//     RED.ADD (no return). Integer addition is commutative -> bitwise
//     deterministic independent of arrival order. One u64 load replaces the
//     16-float partial gather.
//   * Two-level election (tile, then global) for the loss reduction; all fp
//     sums fixed-order.
//
// Grid (32 chunks x 16 i-tiles) = 512 blocks x 256 thr; occupancy limit 4
// blocks/SM -> capacity 592 blocks >= 512: whole grid co-resident, spins safe.
// No device allocations, graph-capturable, deterministic.

#define N        8192
#define CHUNK    256
#define NCHUNK   32
#define BLOCK    256
#define TILE     512           // i's per tile (2 per thread)
#define NTILE    16            // N / TILE
#define EPS_F    1e-8f
#define FPSCALE  4294967296.0  // 2^32

__device__ float              g_ts[N];                    // chunk-sorted t
__device__ float              g_sf[NCHUNK * (CHUNK + 1)]; // suffix + sentinel
__device__ unsigned long long g_S[N];                     // fixed-point S_i
__device__ float              g_bsum[NTILE];
__device__ int                g_flag[NCHUNK];             // zero-init
__device__ int                g_done_it[NTILE];           // zero-init
__device__ int                g_done_final;               // zero-init

__device__ __forceinline__ void bstage_shfl(float& key, float& val,
                                            int j, int k, int tid) {
    const float bk = __shfl_xor_sync(0xffffffffu, key, j);
    const float bv = __shfl_xor_sync(0xffffffffu, val, j);
    const bool lower = (tid & j) == 0;
    const bool up    = (tid & k) == 0;
    const bool take_b = (up == lower) ? (bk < key) : (bk > key);
    if (take_b) { key = bk; val = bv; }
}

__global__ __launch_bounds__(BLOCK, 4) void cox_fused(
    const float* __restrict__ risk,
    const float* __restrict__ t,
    const float* __restrict__ e,
    float* __restrict__ out,
    int n)
{
    __shared__ float sk[CHUNK];
    __shared__ float sv[CHUNK];
    __shared__ float ts[CHUNK];
    __shared__ float sf[CHUNK + 1];
    __shared__ float red[BLOCK];
    __shared__ float wsum[BLOCK / 32];
    __shared__ int   flag;

    const int c    = blockIdx.x;         // chunk  0..31
    const int ib   = blockIdx.y;         // i-tile 0..15
    const int tid  = threadIdx.x;
    const int lane = tid & 31;
    const int w    = tid >> 5;

    // prefetch search keys before any waiting (latency overlapped with spin)
    const int   i0 = ib * TILE + tid;
    const int   i1 = i0 + BLOCK;
    const float t0 = t[i0];
    const float t1 = t[i1];

    if (ib == 0) {
        // ============== sorter block for chunk c ==========================
        const int base = c * CHUNK;
        float key = t[base + tid];
        float val = expf(risk[base + tid]);

        // k = 2..32 entirely in registers
#pragma unroll
        for (int k = 2; k <= 32; k <<= 1)
#pragma unroll
            for (int j = k >> 1; j >= 1; j >>= 1)
                bstage_shfl(key, val, j, k, tid);

        // k = 64..256: j>=32 via smem (6 stages), j<32 via shfl
        for (int k = 64; k <= CHUNK; k <<= 1) {
            for (int j = k >> 1; j >= 32; j >>= 1) {
                sk[tid] = key; sv[tid] = val;
                __syncthreads();
                const int p = tid ^ j;
                const float bk = sk[p], bv = sv[p];
                const bool lower = (tid & j) == 0;
                const bool up    = (tid & k) == 0;
                const bool take_b = (up == lower) ? (bk < key) : (bk > key);
                if (take_b) { key = bk; val = bv; }
                __syncthreads();
            }
#pragma unroll
            for (int j = 16; j >= 1; j >>= 1)
                bstage_shfl(key, val, j, k, tid);
        }

        // inclusive suffix scan: warp shfl + cross-warp fixup
        float v = val;
#pragma unroll
        for (int off = 1; off < 32; off <<= 1) {
            const float x = __shfl_down_sync(0xffffffffu, v, off);
            if (lane + off < 32) v += x;
        }
        if (lane == 0) wsum[w] = v;
        __syncthreads();
        float add = 0.0f;
        for (int ww = w + 1; ww < BLOCK / 32; ww++)   // fixed order
            add += wsum[ww];
        v += add;

        // publish: smem (for own search) + global (for other tiles)
        ts[tid] = key;
        sf[tid] = v;
        if (tid == 0) sf[CHUNK] = 0.0f;
        g_ts[c * CHUNK + tid] = key;
        g_sf[c * (CHUNK + 1) + tid] = v;
        if (tid == 0) g_sf[c * (CHUNK + 1) + CHUNK] = 0.0f;
        __syncthreads();
        if (tid == 0)      // release: orders all prior STGs before the flag
            asm volatile("st.global.release.gpu.b32 [%0], %1;"
                         :: "l"(&g_flag[c]), "r"(1) : "memory");
    } else {
        // ============== searcher block: wait for chunk c, stage tables ====
        if (tid == 0) {
            int v;
            do {
                asm volatile("ld.global.acquire.gpu.b32 %0, [%1];"
                             : "=r"(v) : "l"(&g_flag[c]) : "memory");
            } while (v == 0);
        }
        __syncthreads();
        ts[tid] = g_ts[c * CHUNK + tid];
        for (int idx = tid; idx < CHUNK + 1; idx += BLOCK)
            sf[idx] = g_sf[c * (CHUNK + 1) + idx];
        __syncthreads();
    }

    // ================= search: two interleaved lower_bounds ===============
    int p0 = 0, p1 = 0;
#pragma unroll
    for (int bit = CHUNK >> 1; bit >= 1; bit >>= 1) {
        const float a0 = ts[p0 + bit - 1];
        const float a1 = ts[p1 + bit - 1];
        if (a0 < t0) p0 += bit;
        if (a1 < t1) p1 += bit;
    }
    if (ts[p0] < t0) p0++;               // allow pos == CHUNK
    if (ts[p1] < t1) p1++;

    // fixed-point contribution: integer adds -> order-independent result
    const unsigned long long q0 =
        (unsigned long long)__double2ll_rn((double)sf[p0] * FPSCALE);
    const unsigned long long q1 =
        (unsigned long long)__double2ll_rn((double)sf[p1] * FPSCALE);
    atomicAdd(&g_S[i0], q0);             // RED.ADD.64, no return
    atomicAdd(&g_S[i1], q1);

    // ================= tile election (32 chunk-blocks per tile) ===========
    __threadfence();
    __syncthreads();
    if (tid == 0)
        flag = (atomicAdd(&g_done_it[ib], 1) == NCHUNK - 1);
    __syncthreads();
    if (!flag) return;

    __threadfence();                     // acquire: all RED.ADDs visible

    const unsigned long long v0 = g_S[i0];
    const unsigned long long v1 = g_S[i1];
    g_S[i0] = 0ull;                      // reset for next graph replay
    g_S[i1] = 0ull;

    const float S0 = (float)((double)v0 * (1.0 / FPSCALE));
    const float S1 = (float)((double)v1 * (1.0 / FPSCALE));

    float acc = (risk[i0] - logf(S0 + EPS_F)) * e[i0]
              + (risk[i1] - logf(S1 + EPS_F)) * e[i1];

    // fixed-order block reduction of 256 values
    red[tid] = acc;
    __syncthreads();
    if (tid < 128) red[tid] += red[tid + 128];
    __syncthreads();
    if (tid < 64)  red[tid] += red[tid + 64];
    __syncthreads();
    if (tid < 32) {
        float v = red[tid] + red[tid + 32];
#pragma unroll
        for (int off = 16; off > 0; off >>= 1)
            v += __shfl_down_sync(0xffffffffu, v, off);

        if (tid == 0) {
            g_bsum[ib] = v;
            __threadfence();
            if (atomicAdd(&g_done_final, 1) == NTILE - 1) {
                __threadfence();
                float total = 0.0f;
                for (int b = 0; b < NTILE; b++)   // fixed order
                    total += __ldcg(&g_bsum[b]);
                out[0] = -total / (float)n;

                // reset all control state for the next graph replay
                g_done_final = 0;
                for (int b = 0; b < NTILE; b++)  g_done_it[b] = 0;
                for (int cc = 0; cc < NCHUNK; cc++) g_flag[cc] = 0;
                __threadfence();
            }
        }
    }
}

// ---------------------------------------------------------------- launch
extern "C" void kernel_launch(void* const* d_in, const int* in_sizes, int n_in,
                              void* d_out, int out_size) {
    const float* risk = (const float*)d_in[0];
    const float* t    = (const float*)d_in[1];
    const float* e    = (const float*)d_in[2];
    float* out = (float*)d_out;

    const int n = in_sizes[0];   // 8192

    cox_fused<<<dim3(NCHUNK, NTILE), BLOCK>>>(risk, t, e, out, n);
}

// round 17
// speedup vs baseline: 1.1102x; 1.0153x over previous
#include <cuda_runtime.h>

// Cox partial-likelihood loss, n = 8192 — single fused kernel, critical-path
// optimized:
//   * CHUNK=256 (32 chunks): shorter bitonic network (36 stages, only 6 smem
//     barrier stages) and 9-step searches.
//   * Per-chunk ready flags (st.release / ld.acquire) instead of a global
//     sort barrier — search of chunk c starts the moment chunk c is sorted.
//   * Chunk contributions accumulated into g_S[i] as FIXED-POINT u64 via
//     RED.ADD (no return). Integer addition is commutative -> bitwise
//     deterministic independent of arrival order. One u64 load replaces the
//     16-float partial gather.
//   * Two-level election (tile, then global) for the loss reduction; all fp
//     sums fixed-order.
//
// Grid (32 chunks x 16 i-tiles) = 512 blocks x 256 thr; occupancy limit 4
// blocks/SM -> capacity 592 blocks >= 512: whole grid co-resident, spins safe.
// No device allocations, graph-capturable, deterministic.

#define N        8192
#define CHUNK    256
#define NCHUNK   32
#define BLOCK    256
#define TILE     512           // i's per tile (2 per thread)
#define NTILE    16            // N / TILE
#define EPS_F    1e-8f
#define FPSCALE  4294967296.0  // 2^32

__device__ float              g_ts[N];                    // chunk-sorted t
__device__ float              g_sf[NCHUNK * (CHUNK + 1)]; // suffix + sentinel
__device__ unsigned long long g_S[N];                     // fixed-point S_i
__device__ float              g_bsum[NTILE];
__device__ int                g_flag[NCHUNK];             // zero-init
__device__ int                g_done_it[NTILE];           // zero-init
__device__ int                g_done_final;               // zero-init

__device__ __forceinline__ void bstage_shfl(float& key, float& val,
                                            int j, int k, int tid) {
    const float bk = __shfl_xor_sync(0xffffffffu, key, j);
    const float bv = __shfl_xor_sync(0xffffffffu, val, j);
    const bool lower = (tid & j) == 0;
    const bool up    = (tid & k) == 0;
    const bool take_b = (up == lower) ? (bk < key) : (bk > key);
    if (take_b) { key = bk; val = bv; }
}

__global__ __launch_bounds__(BLOCK, 4) void cox_fused(
    const float* __restrict__ risk,
    const float* __restrict__ t,
    const float* __restrict__ e,
    float* __restrict__ out,
    int n)
{
    __shared__ float sk[CHUNK];
    __shared__ float sv[CHUNK];
    __shared__ float ts[CHUNK];
    __shared__ float sf[CHUNK + 1];
    __shared__ float red[BLOCK];
    __shared__ float wsum[BLOCK / 32];
    __shared__ int   flag;

    const int c    = blockIdx.x;         // chunk  0..31
    const int ib   = blockIdx.y;         // i-tile 0..15
    const int tid  = threadIdx.x;
    const int lane = tid & 31;
    const int w    = tid >> 5;

    // prefetch search keys before any waiting (latency overlapped with spin)
    const int   i0 = ib * TILE + tid;
    const int   i1 = i0 + BLOCK;
    const float t0 = t[i0];
    const float t1 = t[i1];

    if (ib == 0) {
        // ============== sorter block for chunk c ==========================
        const int base = c * CHUNK;
        float key = t[base + tid];
        float val = expf(risk[base + tid]);

        // k = 2..32 entirely in registers
#pragma unroll
        for (int k = 2; k <= 32; k <<= 1)
#pragma unroll
            for (int j = k >> 1; j >= 1; j >>= 1)
                bstage_shfl(key, val, j, k, tid);

        // k = 64..256: j>=32 via smem (6 stages), j<32 via shfl
        for (int k = 64; k <= CHUNK; k <<= 1) {
            for (int j = k >> 1; j >= 32; j >>= 1) {
                sk[tid] = key; sv[tid] = val;
                __syncthreads();
                const int p = tid ^ j;
                const float bk = sk[p], bv = sv[p];
                const bool lower = (tid & j) == 0;
                const bool up    = (tid & k) == 0;
                const bool take_b = (up == lower) ? (bk < key) : (bk > key);
                if (take_b) { key = bk; val = bv; }
                __syncthreads();
            }
#pragma unroll
            for (int j = 16; j >= 1; j >>= 1)
                bstage_shfl(key, val, j, k, tid);
        }

        // inclusive suffix scan: warp shfl + cross-warp fixup
        float v = val;
#pragma unroll
        for (int off = 1; off < 32; off <<= 1) {
            const float x = __shfl_down_sync(0xffffffffu, v, off);
            if (lane + off < 32) v += x;
        }
        if (lane == 0) wsum[w] = v;
        __syncthreads();
        float add = 0.0f;
        for (int ww = w + 1; ww < BLOCK / 32; ww++)   // fixed order
            add += wsum[ww];
        v += add;

        // publish: smem (for own search) + global (for other tiles)
        ts[tid] = key;
        sf[tid] = v;
        if (tid == 0) sf[CHUNK] = 0.0f;
        g_ts[c * CHUNK + tid] = key;
        g_sf[c * (CHUNK + 1) + tid] = v;
        if (tid == 0) g_sf[c * (CHUNK + 1) + CHUNK] = 0.0f;
        __syncthreads();
        if (tid == 0)      // release: orders all prior STGs before the flag
            asm volatile("st.global.release.gpu.b32 [%0], %1;"
                         :: "l"(&g_flag[c]), "r"(1) : "memory");
    } else {
        // ============== searcher block: wait for chunk c, stage tables ====
        if (tid == 0) {
            int v;
            do {
                asm volatile("ld.global.acquire.gpu.b32 %0, [%1];"
                             : "=r"(v) : "l"(&g_flag[c]) : "memory");
            } while (v == 0);
        }
        __syncthreads();
        ts[tid] = g_ts[c * CHUNK + tid];
        for (int idx = tid; idx < CHUNK + 1; idx += BLOCK)
            sf[idx] = g_sf[c * (CHUNK + 1) + idx];
        __syncthreads();
    }

    // ================= search: two interleaved lower_bounds ===============
    int p0 = 0, p1 = 0;
#pragma unroll
    for (int bit = CHUNK >> 1; bit >= 1; bit >>= 1) {
        const float a0 = ts[p0 + bit - 1];
        const float a1 = ts[p1 + bit - 1];
        if (a0 < t0) p0 += bit;
        if (a1 < t1) p1 += bit;
    }
    if (ts[p0] < t0) p0++;               // allow pos == CHUNK
    if (ts[p1] < t1) p1++;

    // fixed-point contribution: integer adds -> order-independent result
    const unsigned long long q0 =
        (unsigned long long)__double2ll_rn((double)sf[p0] * FPSCALE);
    const unsigned long long q1 =
        (unsigned long long)__double2ll_rn((double)sf[p1] * FPSCALE);
    atomicAdd(&g_S[i0], q0);             // RED.ADD.64, no return
    atomicAdd(&g_S[i1], q1);

    // ================= tile election (32 chunk-blocks per tile) ===========
    __threadfence();
    __syncthreads();
    if (tid == 0)
        flag = (atomicAdd(&g_done_it[ib], 1) == NCHUNK - 1);
    __syncthreads();
    if (!flag) return;

    __threadfence();                     // acquire: all RED.ADDs visible

    const unsigned long long v0 = g_S[i0];
    const unsigned long long v1 = g_S[i1];
    g_S[i0] = 0ull;                      // reset for next graph replay
    g_S[i1] = 0ull;

    const float S0 = (float)((double)v0 * (1.0 / FPSCALE));
    const float S1 = (float)((double)v1 * (1.0 / FPSCALE));

    float acc = (risk[i0] - logf(S0 + EPS_F)) * e[i0]
              + (risk[i1] - logf(S1 + EPS_F)) * e[i1];

    // fixed-order block reduction of 256 values
    red[tid] = acc;
    __syncthreads();
    if (tid < 128) red[tid] += red[tid + 128];
    __syncthreads();
    if (tid < 64)  red[tid] += red[tid + 64];
    __syncthreads();
    if (tid < 32) {
        float v = red[tid] + red[tid + 32];
#pragma unroll
        for (int off = 16; off > 0; off >>= 1)
            v += __shfl_down_sync(0xffffffffu, v, off);

        if (tid == 0) {
            g_bsum[ib] = v;
            __threadfence();
            if (atomicAdd(&g_done_final, 1) == NTILE - 1) {
                __threadfence();
                float total = 0.0f;
                for (int b = 0; b < NTILE; b++)   // fixed order
                    total += __ldcg(&g_bsum[b]);
                out[0] = -total / (float)n;

                // reset all control state for the next graph replay
                g_done_final = 0;
                for (int b = 0; b < NTILE; b++)  g_done_it[b] = 0;
                for (int cc = 0; cc < NCHUNK; cc++) g_flag[cc] = 0;
                __threadfence();
            }
        }
    }
}

// ---------------------------------------------------------------- launch
extern "C" void kernel_launch(void* const* d_in, const int* in_sizes, int n_in,
                              void* d_out, int out_size) {
    const float* risk = (const float*)d_in[0];
    const float* t    = (const float*)d_in[1];
    const float* e    = (const float*)d_in[2];
    float* out = (float*)d_out;

    const int n = in_sizes[0];   // 8192

    cox_fused<<<dim3(NCHUNK, NTILE), BLOCK>>>(risk, t, e, out, n);
}